// round 7
// baseline (speedup 1.0000x reference)
#include <cuda_runtime.h>
#include <cstdint>

// Problem shape (fixed for this dataset):
//   pool: f32  [16, 128, 128, 64]  -> 16,777,216 elements
//   ind : i32  same shape, values in [0, 4,194,304)
//   out : f32  [16, 256, 256, 64]  -> 67,108,864 elements (256 MB)
// Per-batch flat scatter-ADD (duplicates sum).
//
// Measured walls (R3-R6): divergent-atomic rate ~2.1 cyc/atomic/SM is
// invariant to occupancy/ILP/grid shape => scatter floor ~132 us. This round
// removes the remaining serialized-zero overhead:
//  - 4 chunks x 4 batches; kernel k scatters chunk k AND zeroes chunk k+1.
//  - zeroing is spread uniformly over ALL blocks (16 KB each, issued at
//    block start) so store wavefronts interleave into atomic-replay gaps
//    instead of forming a tail (R6's dedicated-trailing-blocks mistake).
//  - input loads use __ldcs (evict-first) so 32 MB/chunk of streamed input
//    doesn't evict the 64 MB L2-resident output slice.

static constexpr int  PB_IN_V4_LOG2     = 18;   // per-batch input elems/4 = 2^18
static constexpr int  OUT_FLAT_LOG2     = 22;   // per-batch output elems = 2^22
static constexpr int  BATCHES           = 16;
static constexpr int  BATCHES_PER_CHUNK = 4;
static constexpr int  NCHUNKS           = BATCHES / BATCHES_PER_CHUNK;   // 4

static constexpr int  CHUNK_IN_V4    = BATCHES_PER_CHUNK << PB_IN_V4_LOG2;        // 1,048,576
static constexpr long CHUNK_OUT_ELEM = (long)BATCHES_PER_CHUNK << OUT_FLAT_LOG2;  // 16,777,216
static constexpr int  CHUNK_OUT_V4   = (int)(CHUNK_OUT_ELEM / 4);                 // 4,194,304

static constexpr int  THREADS = 256;
static constexpr int  BLOCKS  = CHUNK_IN_V4 / THREADS;          // 4096
static constexpr int  ZERO_V4_PER_BLOCK = CHUNK_OUT_V4 / BLOCKS; // 1024 (4/thread)

// ---------------------------------------------------------------------------
// Fused kernel: every block first zeroes its 16 KB slice of the NEXT chunk,
// then scatters its 1024 elements of the CURRENT chunk (R3-proven body).
// zero_dst == nullptr on the last chunk.
// ---------------------------------------------------------------------------
__global__ void __launch_bounds__(THREADS)
unpool_fused(const float4* __restrict__ pool4,
             const int4*   __restrict__ ind4,
             float*        __restrict__ out,
             float4*       __restrict__ zero_dst) {
    const int t = blockIdx.x * blockDim.x + threadIdx.x;

    // ---- zero a slice of chunk k+1 (issued first: fills L1tex gaps) ----
    if (zero_dst != nullptr) {
        const float4 z = make_float4(0.f, 0.f, 0.f, 0.f);
        int zbase = blockIdx.x * ZERO_V4_PER_BLOCK + threadIdx.x;
        #pragma unroll
        for (int j = 0; j < ZERO_V4_PER_BLOCK / THREADS; ++j) {
            zero_dst[zbase + j * THREADS] = z;
        }
    }

    // ---- scatter chunk k ----
    // Streaming loads: evict-first so inputs don't displace the output slice.
    float4 p = __ldcs(pool4 + t);
    int4   i = __ldcs(ind4 + t);

    long base = (long)(t >> PB_IN_V4_LOG2) << OUT_FLAT_LOG2;

    atomicAdd(out + base + (long)(unsigned)i.x, p.x);
    atomicAdd(out + base + (long)(unsigned)i.y, p.y);
    atomicAdd(out + base + (long)(unsigned)i.z, p.z);
    atomicAdd(out + base + (long)(unsigned)i.w, p.w);
}

// Standalone zero for chunk 0 (pipeline head, wide grid).
__global__ void __launch_bounds__(THREADS)
zero_chunk(float4* __restrict__ dst) {
    const float4 z = make_float4(0.f, 0.f, 0.f, 0.f);
    int t = blockIdx.x * blockDim.x + threadIdx.x;
    const int stride = gridDim.x * blockDim.x;
    for (; t < CHUNK_OUT_V4; t += stride) {
        dst[t] = z;
    }
}

// ---------------------------------------------------------------------------
extern "C" void kernel_launch(void* const* d_in, const int* in_sizes, int n_in,
                              void* d_out, int out_size) {
    const float4* pool4 = (const float4*)d_in[0];
    const int4*   ind4  = (const int4*)d_in[1];
    float*        out   = (float*)d_out;

    // Zero chunk 0 up front (latency-exposed head: ~10 us at DRAM/L2 cap).
    zero_chunk<<<4096, THREADS>>>((float4*)out);

    for (int c = 0; c < NCHUNKS; ++c) {
        float*  out_cur = out + (long)c * CHUNK_OUT_ELEM;
        float4* zero_nx = (c + 1 < NCHUNKS)
                        ? (float4*)(out + (long)(c + 1) * CHUNK_OUT_ELEM)
                        : nullptr;

        unpool_fused<<<BLOCKS, THREADS>>>(
            pool4 + (long)c * CHUNK_IN_V4,
            ind4  + (long)c * CHUNK_IN_V4,
            out_cur,
            zero_nx);
    }
}

// round 8
// speedup vs baseline: 1.2003x; 1.2003x over previous
#include <cuda_runtime.h>
#include <cstdint>

// Problem shape (fixed for this dataset):
//   pool: f32  [16, 128, 128, 64]  -> 16,777,216 elements
//   ind : i32  same shape, values in [0, 4,194,304)
//   out : f32  [16, 256, 256, 64]  -> 67,108,864 elements (256 MB)
// Per-batch flat scatter-ADD (duplicates sum).
//
// Measured walls (R3-R7):
//  - divergent-atomic rate ~2.1 cyc/atomic/SM => scatter floor ~17 us per
//    2-batch chunk (~136 us total), invariant to occupancy/ILP/grid shape.
//  - fused zero-next-chunk overlaps nearly free IF the L2 live set fits:
//    2-batch chunks -> 32 (cur) + 32 (next) + ~16 (inputs) = 80 MB < 126 MB.
//    (R7's 4-batch chunks = 128+ MB live set evicted the slice -> DRAM RMW.)
// This round: 8 x 2-batch pipeline, zero of chunk k+1 spread uniformly over
// all of kernel k's blocks (no trailing-block tail), tiny 32 MB head zero.

static constexpr int  PB_IN_V4_LOG2     = 18;   // per-batch input elems/4 = 2^18
static constexpr int  OUT_FLAT_LOG2     = 22;   // per-batch output elems = 2^22
static constexpr int  BATCHES           = 16;
static constexpr int  BATCHES_PER_CHUNK = 2;
static constexpr int  NCHUNKS           = BATCHES / BATCHES_PER_CHUNK;   // 8

static constexpr int  CHUNK_IN_V4    = BATCHES_PER_CHUNK << PB_IN_V4_LOG2;        // 524,288
static constexpr long CHUNK_OUT_ELEM = (long)BATCHES_PER_CHUNK << OUT_FLAT_LOG2;  // 8,388,608
static constexpr int  CHUNK_OUT_V4   = (int)(CHUNK_OUT_ELEM / 4);                 // 2,097,152

static constexpr int  THREADS = 256;
static constexpr int  BLOCKS  = CHUNK_IN_V4 / THREADS;            // 2048
static constexpr int  ZERO_V4_PER_BLOCK = CHUNK_OUT_V4 / BLOCKS;  // 1024 (4/thread)
static constexpr int  ZERO_PER_THREAD   = ZERO_V4_PER_BLOCK / THREADS; // 4

// ---------------------------------------------------------------------------
// Fused kernel: each block loads its inputs, issues its 16 KB zero slice of
// the NEXT chunk (stores fill L1tex gaps while atomics replay), then runs
// the R3-proven 4-atomic scatter body. zero_dst == nullptr on last chunk.
// ---------------------------------------------------------------------------
__global__ void __launch_bounds__(THREADS)
unpool_fused(const float4* __restrict__ pool4,
             const int4*   __restrict__ ind4,
             float*        __restrict__ out,
             float4*       __restrict__ zero_dst) {
    const int t = blockIdx.x * blockDim.x + threadIdx.x;

    // Front-batch input loads (independent -> MLP).
    float4 p = pool4[t];
    int4   i = ind4[t];

    // Zero a uniform slice of chunk k+1 (independent streaming stores).
    if (zero_dst != nullptr) {
        const float4 z = make_float4(0.f, 0.f, 0.f, 0.f);
        int zbase = blockIdx.x * ZERO_V4_PER_BLOCK + threadIdx.x;
        #pragma unroll
        for (int j = 0; j < ZERO_PER_THREAD; ++j) {
            zero_dst[zbase + j * THREADS] = z;
        }
    }

    // Scatter chunk k (atomics into L2-resident 32 MB slice).
    long base = (long)(t >> PB_IN_V4_LOG2) << OUT_FLAT_LOG2;

    atomicAdd(out + base + (long)(unsigned)i.x, p.x);
    atomicAdd(out + base + (long)(unsigned)i.y, p.y);
    atomicAdd(out + base + (long)(unsigned)i.z, p.z);
    atomicAdd(out + base + (long)(unsigned)i.w, p.w);
}

// Head zero for chunk 0 only (32 MB, ~5 us).
__global__ void __launch_bounds__(THREADS)
zero_chunk(float4* __restrict__ dst) {
    const float4 z = make_float4(0.f, 0.f, 0.f, 0.f);
    int t = blockIdx.x * blockDim.x + threadIdx.x;
    const int stride = gridDim.x * blockDim.x;
    for (; t < CHUNK_OUT_V4; t += stride) {
        dst[t] = z;
    }
}

// ---------------------------------------------------------------------------
extern "C" void kernel_launch(void* const* d_in, const int* in_sizes, int n_in,
                              void* d_out, int out_size) {
    const float4* pool4 = (const float4*)d_in[0];
    const int4*   ind4  = (const int4*)d_in[1];
    float*        out   = (float*)d_out;

    // Zero chunk 0 up front (pipeline head).
    zero_chunk<<<2048, THREADS>>>((float4*)out);

    for (int c = 0; c < NCHUNKS; ++c) {
        float*  out_cur = out + (long)c * CHUNK_OUT_ELEM;
        float4* zero_nx = (c + 1 < NCHUNKS)
                        ? (float4*)(out + (long)(c + 1) * CHUNK_OUT_ELEM)
                        : nullptr;

        unpool_fused<<<BLOCKS, THREADS>>>(
            pool4 + (long)c * CHUNK_IN_V4,
            ind4  + (long)c * CHUNK_IN_V4,
            out_cur,
            zero_nx);
    }
}

// round 9
// speedup vs baseline: 1.3364x; 1.1134x over previous
#include <cuda_runtime.h>
#include <cstdint>

// Problem shape (fixed for this dataset):
//   pool: f32  [16, 128, 128, 64]  -> 16,777,216 elements
//   ind : i32  same shape, values in [0, 4,194,304)
//   out : f32  [16, 256, 256, 64]  -> 67,108,864 elements (256 MB)
// Per-batch flat scatter-ADD (duplicates sum).
//
// Model (R3-R8 measured):
//  - L1tex wavefront engine is THE per-SM bottleneck: divergent atomics cost
//    ~2.1 cyc/wf, and ordinary zero stores compete 1:1 with them (fusion via
//    STG proved wavefront-conserving: no win). Atomic floor ~132 us total.
//  - Output slice must stay L2-resident or LTS backpressure bites (R7).
// This round: zero chunk k+1 via TMA bulk stores (cp.async.bulk, UTMASTG) —
// a global-write path that bypasses the SM L1tex wavefront engine. Each
// scatter block fills a 16 KB SMEM zero buffer and issues ONE bulk store,
// overlapped with its atomics. 8 chunks x 2 batches keeps the L2 live set
// at 32 (cur) + 32 (next) + 16 (inputs) = 80 MB < 126 MB.

static constexpr int  PB_IN_V4_LOG2     = 18;   // per-batch input elems/4 = 2^18
static constexpr int  OUT_FLAT_LOG2     = 22;   // per-batch output elems = 2^22
static constexpr int  BATCHES           = 16;
static constexpr int  BATCHES_PER_CHUNK = 2;
static constexpr int  NCHUNKS           = BATCHES / BATCHES_PER_CHUNK;   // 8

static constexpr int  CHUNK_IN_V4     = BATCHES_PER_CHUNK << PB_IN_V4_LOG2;        // 524,288
static constexpr long CHUNK_OUT_ELEM  = (long)BATCHES_PER_CHUNK << OUT_FLAT_LOG2;  // 8,388,608
static constexpr long CHUNK_OUT_BYTES = CHUNK_OUT_ELEM * 4;                        // 32 MB

static constexpr int  THREADS = 256;
static constexpr int  BLOCKS  = CHUNK_IN_V4 / THREADS;                 // 2048
static constexpr int  ZERO_BYTES_PER_BLOCK = (int)(CHUNK_OUT_BYTES / BLOCKS); // 16384
static constexpr int  ZBUF_F4 = ZERO_BYTES_PER_BLOCK / 16;             // 1024 float4

// ---------------------------------------------------------------------------
// Fused kernel: scatter chunk k (R3-proven body) + TMA-bulk-zero a 16 KB
// slice of chunk k+1. The bulk store is issued BEFORE the atomics so it
// drains through the (idle) TMA/LTS write path while the SM grinds replays.
// ---------------------------------------------------------------------------
__global__ void __launch_bounds__(THREADS)
unpool_scatter_tmazero(const float4* __restrict__ pool4,
                       const int4*   __restrict__ ind4,
                       float*        __restrict__ out,
                       char*         __restrict__ zero_base,   // nullptr on last chunk
                       int            do_zero) {
    __shared__ __align__(16) float4 zbuf[ZBUF_F4];   // 16 KB of zeros

    const int t = blockIdx.x * blockDim.x + threadIdx.x;

    // Front-batch input loads (independent -> MLP). Evict-first: keep L2 for
    // the output slices.
    float4 p = __ldcs(pool4 + t);
    int4   i = __ldcs(ind4 + t);

    if (do_zero) {
        // Fill SMEM zero buffer (4 STS.128 per thread — cheap, smem port).
        const float4 z = make_float4(0.f, 0.f, 0.f, 0.f);
        #pragma unroll
        for (int j = 0; j < ZBUF_F4 / THREADS; ++j) {
            zbuf[threadIdx.x + j * THREADS] = z;
        }
        __syncthreads();
        // Make generic-proxy SMEM writes visible to the async (TMA) proxy.
        asm volatile("fence.proxy.async.shared::cta;" ::: "memory");

        if (threadIdx.x == 0) {
            char* gdst = zero_base + (long)blockIdx.x * ZERO_BYTES_PER_BLOCK;
            uint32_t saddr;
            asm("{ .reg .u64 tmp; cvta.to.shared.u64 tmp, %1; cvt.u32.u64 %0, tmp; }"
                : "=r"(saddr) : "l"(zbuf));
            asm volatile(
                "cp.async.bulk.global.shared::cta.bulk_group [%0], [%1], %2;"
                :: "l"(gdst), "r"(saddr), "r"((uint32_t)ZERO_BYTES_PER_BLOCK)
                : "memory");
            asm volatile("cp.async.bulk.commit_group;" ::: "memory");
        }
    }

    // Scatter chunk k (atomics into L2-resident 32 MB slice).
    long base = (long)(t >> PB_IN_V4_LOG2) << OUT_FLAT_LOG2;

    atomicAdd(out + base + (long)(unsigned)i.x, p.x);
    atomicAdd(out + base + (long)(unsigned)i.y, p.y);
    atomicAdd(out + base + (long)(unsigned)i.z, p.z);
    atomicAdd(out + base + (long)(unsigned)i.w, p.w);

    // Ensure the bulk store has fully landed before the kernel retires
    // (stream order then protects the next chunk's atomics).
    if (do_zero && threadIdx.x == 0) {
        asm volatile("cp.async.bulk.wait_group 0;" ::: "memory");
    }
}

// ---------------------------------------------------------------------------
extern "C" void kernel_launch(void* const* d_in, const int* in_sizes, int n_in,
                              void* d_out, int out_size) {
    const float4* pool4 = (const float4*)d_in[0];
    const int4*   ind4  = (const int4*)d_in[1];
    float*        out   = (float*)d_out;

    // Head: zero chunk 0 (32 MB — dirty L2 lines, a few us).
    cudaMemsetAsync(out, 0, CHUNK_OUT_BYTES, 0);

    for (int c = 0; c < NCHUNKS; ++c) {
        float* out_cur = out + (long)c * CHUNK_OUT_ELEM;
        char*  zero_nx = (c + 1 < NCHUNKS)
                       ? (char*)(out + (long)(c + 1) * CHUNK_OUT_ELEM)
                       : nullptr;

        unpool_scatter_tmazero<<<BLOCKS, THREADS>>>(
            pool4 + (long)c * CHUNK_IN_V4,
            ind4  + (long)c * CHUNK_IN_V4,
            out_cur,
            zero_nx,
            zero_nx != nullptr ? 1 : 0);
    }
}